// round 8
// baseline (speedup 1.0000x reference)
#include <cuda_runtime.h>
#include <cuda_fp16.h>
#include <cstdint>

// ---------------- problem constants ----------------
#define SB   4
#define SS   2048
#define SEQ  2046
#define NH   12
#define ND   64
#define ROWSTRIDE (NH*ND)        // 768 elems between consecutive l in v
#define NV   (SB*SS*NH*ND)       // 6291456 elements of v

// ---------------- GEMM tiling ----------------
#define TM    128                // j rows per CTA
#define TN    64                 // c cols per CTA
#define KC    64                 // l per chunk
#define NCHUNK (SS / KC)         // 32
#define THREADS 256

#define A_STR  72                // halves per j row (64 k + 8 pad)
#define B_STR  72                // halves per k row (64 c + 8 pad)
#define A_BYTES (TM * A_STR * 2)          // 18432
#define B_BYTES (KC * B_STR * 2)          // 9216
#define DYN_BYTES (2*A_BYTES + 2*B_BYTES) // 55296

// fp16 copy of v (device-global scratch)
__device__ __half vt_h[NV];

__device__ __forceinline__ uint32_t smem_u32(const void* p) {
    uint32_t a;
    asm("{ .reg .u64 t; cvta.to.shared.u64 t, %1; cvt.u32.u64 %0, t; }"
        : "=r"(a) : "l"(p));
    return a;
}
__device__ __forceinline__ void cp_async16(uint32_t dst, const void* src) {
    asm volatile("cp.async.ca.shared.global [%0], [%1], 16;"
                 :: "r"(dst), "l"(src) : "memory");
}
#define CP_COMMIT() asm volatile("cp.async.commit_group;" ::: "memory")
#define CP_WAIT0()  asm volatile("cp.async.wait_group 0;" ::: "memory")

__device__ __forceinline__ void ldsm_x4(uint32_t* r, uint32_t addr) {
    asm volatile("ldmatrix.sync.aligned.m8n8.x4.shared.b16 {%0,%1,%2,%3}, [%4];"
                 : "=r"(r[0]), "=r"(r[1]), "=r"(r[2]), "=r"(r[3]) : "r"(addr));
}
__device__ __forceinline__ void ldsm_x4_t(uint32_t* r, uint32_t addr) {
    asm volatile("ldmatrix.sync.aligned.m8n8.x4.trans.shared.b16 {%0,%1,%2,%3}, [%4];"
                 : "=r"(r[0]), "=r"(r[1]), "=r"(r[2]), "=r"(r[3]) : "r"(addr));
}
__device__ __forceinline__ void mma_f16(float* d, const uint32_t* a,
                                        const uint32_t* b) {
    asm volatile(
        "mma.sync.aligned.m16n8k16.row.col.f32.f16.f16.f32 "
        "{%0,%1,%2,%3}, {%4,%5,%6,%7}, {%8,%9}, {%0,%1,%2,%3};"
        : "+f"(d[0]), "+f"(d[1]), "+f"(d[2]), "+f"(d[3])
        : "r"(a[0]), "r"(a[1]), "r"(a[2]), "r"(a[3]), "r"(b[0]), "r"(b[1]));
}

// ---------------------------------------------------------------------------
// convert v (fp32) -> vt_h (fp16); 16 elements per thread
// ---------------------------------------------------------------------------
__global__ __launch_bounds__(256) void cvt_kernel(const float* __restrict__ v) {
    int i = (blockIdx.x * 256 + threadIdx.x) * 16;
    float4 x0 = *(const float4*)(v + i);
    float4 x1 = *(const float4*)(v + i + 4);
    float4 x2 = *(const float4*)(v + i + 8);
    float4 x3 = *(const float4*)(v + i + 12);
    __half2 h[8];
    h[0] = __floats2half2_rn(x0.x, x0.y);  h[1] = __floats2half2_rn(x0.z, x0.w);
    h[2] = __floats2half2_rn(x1.x, x1.y);  h[3] = __floats2half2_rn(x1.z, x1.w);
    h[4] = __floats2half2_rn(x2.x, x2.y);  h[5] = __floats2half2_rn(x2.z, x2.w);
    h[6] = __floats2half2_rn(x3.x, x3.y);  h[7] = __floats2half2_rn(x3.z, x3.w);
    *(uint4*)(vt_h + i)     = *(uint4*)h;
    *(uint4*)(vt_h + i + 8) = *(uint4*)(h + 4);
}

// ---------------------------------------------------------------------------
// pbv[n,j,h,d] = sum_l w[h,|l-j|] * v[n,l,h,d] as per-head Toeplitz GEMM.
// grid (16 j-tiles, 4 c-quarters, 12 heads); CTA 128x64, 8 warps of 32x32.
// KC=64 chunks, double-buffered, cp.async B, 3 CTAs/SM.
// ---------------------------------------------------------------------------
__global__ __launch_bounds__(THREADS, 3) void pbv_mma(const float* __restrict__ w,
                                                      float* __restrict__ out) {
    __shared__ __half wsh[SS];                  // 4 KB fp16 w row
    extern __shared__ char dyn[];               // A0 | A1 | B0 | B1

    const int t    = threadIdx.x;
    const int wid  = t >> 5, lane = t & 31;
    const int g    = lane >> 2, t4 = lane & 3;
    const int wm   = wid >> 1;                  // 0..3 -> 32-row slab
    const int wn   = wid & 1;                   // 0..1 -> 32-col slab
    const int l15  = lane & 15, lhi = lane >> 4;

    const int jt = blockIdx.x, ch = blockIdx.y, h = blockIdx.z;
    const int j0 = jt * TM;
    const int c0 = ch * TN;

    {
        const float* wrow = w + (size_t)h * SS;
        for (int i = t; i < SS; i += THREADS) wsh[i] = __float2half_rn(wrow[i]);
    }
    __syncthreads();

    const __half* vtb = vt_h + h * ND;          // + (n*SS + l)*ROWSTRIDE + d
    const uint32_t sb = smem_u32(dyn);

    // ---- stage chunk `c` into buffer c&1
    auto stage = [&](int c) {
        const int k0 = c * KC;
        __half2* Ab = (__half2*)(dyn + (c & 1) * A_BYTES);
#pragma unroll
        for (int i = 0; i < 16; i++) {
            int e  = t + i * THREADS;           // 0..4095
            int kp = e & 31, j = e >> 5;        // kp: half2 pair, j 0..127
            int jg = j0 + j;
            int l0 = k0 + 2 * kp;
            int d0 = l0 - jg;     int a0i = d0 < 0 ? -d0 : d0;
            int d1 = d0 + 1;      int a1i = d1 < 0 ? -d1 : d1;
            __half v0 = (l0 >= 1     && l0     <= SEQ) ? wsh[a0i] : __half(0.f);
            __half v1 = (l0 + 1 >= 1 && l0 + 1 <= SEQ) ? wsh[a1i] : __half(0.f);
            Ab[j * (A_STR / 2) + kp] = __halves2half2(v0, v1);
        }
        const uint32_t Bbase = sb + 2 * A_BYTES + (c & 1) * B_BYTES;
#pragma unroll
        for (int q = 0; q < 2; q++) {
            int fi = t + q * THREADS;           // 0..511, 16B slots
            int k  = fi >> 3, c8 = fi & 7;      // 64 rows x 8 slots
            int cc = c0 + c8 * 8;
            int n  = cc >> 6, d = cc & 63;
            const __half* src = vtb + ((size_t)n * SS + (k0 + k)) * ROWSTRIDE + d;
            cp_async16(Bbase + (uint32_t)(k * B_STR + c8 * 8) * 2, src);
        }
        CP_COMMIT();
    };

    float acc[2][4][4];
#pragma unroll
    for (int mi = 0; mi < 2; mi++)
#pragma unroll
        for (int ni = 0; ni < 4; ni++)
#pragma unroll
            for (int r = 0; r < 4; r++) acc[mi][ni][r] = 0.f;

    const uint32_t aRow = (uint32_t)(wm * 32 + l15);       // + mi*16
    const uint32_t aKof = (uint32_t)(lhi * 8);             // + ks*16
    const uint32_t bRow = (uint32_t)l15;                   // + ks*16
    const uint32_t bCol = (uint32_t)(wn * 32 + lhi * 8);   // + ni2*16

    stage(0);

    for (int c = 0; c < NCHUNK; c++) {
        CP_WAIT0();
        __syncthreads();
        if (c + 1 < NCHUNK) stage(c + 1);

        const uint32_t Ao = sb + (c & 1) * A_BYTES;
        const uint32_t Bo = sb + 2 * A_BYTES + (c & 1) * B_BYTES;

#pragma unroll
        for (int ks = 0; ks < 4; ks++) {
            uint32_t a[2][4], b[4][2];
#pragma unroll
            for (int mi = 0; mi < 2; mi++)
                ldsm_x4(a[mi], Ao + ((aRow + mi * 16) * A_STR + aKof + ks * 16) * 2);
#pragma unroll
            for (int ni2 = 0; ni2 < 2; ni2++) {
                uint32_t r[4];
                ldsm_x4_t(r, Bo + ((bRow + ks * 16) * B_STR + bCol + ni2 * 16) * 2);
                b[2 * ni2][0] = r[0];      b[2 * ni2][1] = r[1];
                b[2 * ni2 + 1][0] = r[2];  b[2 * ni2 + 1][1] = r[3];
            }
#pragma unroll
            for (int mi = 0; mi < 2; mi++)
#pragma unroll
                for (int ni = 0; ni < 4; ni++)
                    mma_f16(acc[mi][ni], a[mi], b[ni]);
        }
    }

    // ---- epilogue: acc -> out[n, j, h, d]
#pragma unroll
    for (int mi = 0; mi < 2; mi++) {
        const int r0 = j0 + wm * 32 + mi * 16 + g;
#pragma unroll
        for (int ni = 0; ni < 4; ni++) {
            const int cc = c0 + wn * 32 + ni * 8 + 2 * t4;
            const int n = cc >> 6, d = cc & 63;
            float* o = out + (((size_t)n * SS) * NH + h) * ND + d;
            if (r0 >= 1 && r0 <= SEQ) {
                float2 s = make_float2(acc[mi][ni][0], acc[mi][ni][1]);
                *(float2*)(o + (size_t)r0 * NH * ND) = s;
            }
            const int r1 = r0 + 8;
            if (r1 >= 1 && r1 <= SEQ) {
                float2 s = make_float2(acc[mi][ni][2], acc[mi][ni][3]);
                *(float2*)(o + (size_t)r1 * NH * ND) = s;
            }
        }
    }
}

// ---------------------------------------------------------------------------
// blocks 0..11: z_pb scan per head; blocks 12..17: zero pbv border rows
// ---------------------------------------------------------------------------
__global__ __launch_bounds__(1024) void zb_kernel(const float* __restrict__ w,
                                                  float* __restrict__ outz,
                                                  float* __restrict__ out) {
    const int b = blockIdx.x;
    if (b >= NH) {   // border: 6 blocks x 1024 cover 8 segs x 768
        int gidx = (b - NH) * 1024 + threadIdx.x;
        if (gidx < 8 * NH * ND) {
            int seg = gidx / (NH * ND);
            int off = gidx % (NH * ND);
            int n = seg >> 1;
            int j = (seg & 1) ? (SS - 1) : 0;
            out[((size_t)(n * SS + j) * NH * ND) + off] = 0.f;
        }
        return;
    }
    const int h = b;
    __shared__ float buf[2][SS];
    for (int i = threadIdx.x; i < SS; i += 1024)
        buf[0][i] = (i < SEQ) ? w[(size_t)h * SS + i] : 0.f;
    __syncthreads();
    int src = 0;
    for (int off = 1; off < SS; off <<= 1) {
        for (int i = threadIdx.x; i < SS; i += 1024) {
            float val = buf[src][i];
            if (i >= off) val += buf[src][i - off];
            buf[src ^ 1][i] = val;
        }
        src ^= 1;
        __syncthreads();
    }
    const float w0 = buf[src][0];
    for (int l = threadIdx.x; l < SS; l += 1024) {
        float zv = 0.f;
        if (l >= 1 && l <= SEQ)
            zv = buf[src][l - 1] + buf[src][SEQ - l] - w0;
        outz[(size_t)l * NH + h] = zv;
    }
}

// ---------------------------------------------------------------------------
extern "C" void kernel_launch(void* const* d_in, const int* in_sizes, int n_in,
                              void* d_out, int out_size) {
    const float* a0 = (const float*)d_in[0];
    const float* a1 = (const float*)d_in[1];
    const float* v = a0;
    const float* w = a1;
    if (n_in >= 2 && in_sizes[0] < in_sizes[1]) { v = a1; w = a0; }

    float* out  = (float*)d_out;
    float* outz = out + (size_t)SB * SS * NH * ND;

    static int configured = 0;
    if (!configured) {
        cudaFuncSetAttribute(pbv_mma, cudaFuncAttributeMaxDynamicSharedMemorySize,
                             DYN_BYTES);
        configured = 1;
    }

    cvt_kernel<<<NV / (256 * 16), 256>>>(v);
    dim3 grid(SS / TM, 256 / TN, NH);        // 16 x 4 x 12 = 768 CTAs
    pbv_mma<<<grid, THREADS, DYN_BYTES>>>(w, out);
    zb_kernel<<<NH + 6, 1024>>>(w, outz, out);
}

// round 9
// speedup vs baseline: 1.4363x; 1.4363x over previous
#include <cuda_runtime.h>
#include <cuda_fp16.h>
#include <cstdint>

// ---------------- problem constants ----------------
#define SB   4
#define SS   2048
#define SEQ  2046
#define NH   12
#define ND   64
#define ROWSTRIDE (NH*ND)        // 768 elems between consecutive l in v
#define NV   (SB*SS*NH*ND)       // 6291456 elements of v

// ---------------- GEMM tiling (R7-proven) ----------------
#define TM    64                 // j rows per CTA
#define TN    128                // c cols per CTA
#define KC    32                 // l per chunk
#define NCHUNK (SS / KC)         // 64
#define THREADS 256

#define A_STR  40                // halves per j row (32 k + 8 pad), 20 words ≡ 4 mod 8: ldsm conflict-free
#define B_STR  136               // halves per k row (128 c + 8 pad), 68 words ≡ 4 mod 8: conflict-free
#define A_BYTES (TM * A_STR * 2)          // 5120
#define B_BYTES (KC * B_STR * 2)          // 8704
#define DYN_BYTES (2*A_BYTES + 2*B_BYTES) // 27648

// fp16 copy of v (device-global scratch)
__device__ __half vt_h[NV];

__device__ __forceinline__ uint32_t smem_u32(const void* p) {
    uint32_t a;
    asm("{ .reg .u64 t; cvta.to.shared.u64 t, %1; cvt.u32.u64 %0, t; }"
        : "=r"(a) : "l"(p));
    return a;
}
__device__ __forceinline__ void cp_async16(uint32_t dst, const void* src) {
    asm volatile("cp.async.ca.shared.global [%0], [%1], 16;"
                 :: "r"(dst), "l"(src) : "memory");
}
#define CP_COMMIT() asm volatile("cp.async.commit_group;" ::: "memory")
#define CP_WAIT0()  asm volatile("cp.async.wait_group 0;" ::: "memory")

__device__ __forceinline__ void ldsm_x4(uint32_t* r, uint32_t addr) {
    asm volatile("ldmatrix.sync.aligned.m8n8.x4.shared.b16 {%0,%1,%2,%3}, [%4];"
                 : "=r"(r[0]), "=r"(r[1]), "=r"(r[2]), "=r"(r[3]) : "r"(addr));
}
__device__ __forceinline__ void ldsm_x4_t(uint32_t* r, uint32_t addr) {
    asm volatile("ldmatrix.sync.aligned.m8n8.x4.trans.shared.b16 {%0,%1,%2,%3}, [%4];"
                 : "=r"(r[0]), "=r"(r[1]), "=r"(r[2]), "=r"(r[3]) : "r"(addr));
}
__device__ __forceinline__ void mma_f16(float* d, const uint32_t* a,
                                        const uint32_t* b) {
    asm volatile(
        "mma.sync.aligned.m16n8k16.row.col.f32.f16.f16.f32 "
        "{%0,%1,%2,%3}, {%4,%5,%6,%7}, {%8,%9}, {%0,%1,%2,%3};"
        : "+f"(d[0]), "+f"(d[1]), "+f"(d[2]), "+f"(d[3])
        : "r"(a[0]), "r"(a[1]), "r"(a[2]), "r"(a[3]), "r"(b[0]), "r"(b[1]));
}

// ---------------------------------------------------------------------------
// convert v (fp32) -> vt_h (fp16); 8 elements per thread (fastest measured)
// ---------------------------------------------------------------------------
__global__ __launch_bounds__(256) void cvt_kernel(const float* __restrict__ v) {
    int i = (blockIdx.x * 256 + threadIdx.x) * 8;
    float4 x0 = *(const float4*)(v + i);
    float4 x1 = *(const float4*)(v + i + 4);
    __half2 h[4];
    h[0] = __floats2half2_rn(x0.x, x0.y);
    h[1] = __floats2half2_rn(x0.z, x0.w);
    h[2] = __floats2half2_rn(x1.x, x1.y);
    h[3] = __floats2half2_rn(x1.z, x1.w);
    *(uint4*)(vt_h + i) = *(uint4*)h;
}

// ---------------------------------------------------------------------------
// pbv[n,j,h,d] = sum_l w[h,|l-j|] * v[n,l,h,d] as per-head Toeplitz GEMM.
// grid (32 j-tiles, 2 c-halves, 12 heads); CTA 64x128 fp16 MMA, 8 warps 32x32.
// Double-buffered, cp.async B, 3 CTAs/SM. Edge chunks take the checked path.
// ---------------------------------------------------------------------------
__global__ __launch_bounds__(THREADS, 3) void pbv_mma(const float* __restrict__ w,
                                                      float* __restrict__ out) {
    __shared__ __half wsh[SS];                  // 4 KB fp16 w row
    extern __shared__ char dyn[];               // A0 | A1 | B0 | B1

    const int t    = threadIdx.x;
    const int wid  = t >> 5, lane = t & 31;
    const int g    = lane >> 2, t4 = lane & 3;
    const int wm   = wid >> 2;                  // 0..1 -> 32-row slab
    const int wn   = wid & 3;                   // 0..3 -> 32-col slab
    const int l15  = lane & 15, lhi = lane >> 4;

    const int jt = blockIdx.x, ch = blockIdx.y, h = blockIdx.z;
    const int j0 = jt * TM;
    const int c0 = ch * TN;

    {
        const float* wrow = w + (size_t)h * SS;
        for (int i = t; i < SS; i += THREADS) wsh[i] = __float2half_rn(wrow[i]);
    }
    __syncthreads();

    const __half* vtb = vt_h + h * ND;          // + (n*SS + l)*ROWSTRIDE + d
    const uint32_t sb = smem_u32(dyn);

    // per-thread A-staging coordinates (constant across chunks)
    const int skp = t & 15;                     // half2 pair within k row
    const int sj  = t >> 4;                     // j row 0..15 (+16*i)

    // ---- stage chunk `c` into buffer c&1
    auto stage = [&](int c) {
        const int k0 = c * KC;
        __half2* Ab = (__half2*)(dyn + (c & 1) * A_BYTES);
        const int l0 = k0 + 2 * skp;
        if (c != 0 && c != NCHUNK - 1) {        // fast path: all l valid
#pragma unroll
            for (int i = 0; i < 4; i++) {
                int jg = j0 + sj + 16 * i;
                int d0 = l0 - jg;     int a0i = d0 < 0 ? -d0 : d0;
                int d1 = d0 + 1;      int a1i = d1 < 0 ? -d1 : d1;
                Ab[(sj + 16 * i) * (A_STR / 2) + skp] =
                    __halves2half2(wsh[a0i], wsh[a1i]);
            }
        } else {                                 // edge chunks: l=0 / l=2047 invalid
#pragma unroll
            for (int i = 0; i < 4; i++) {
                int jg = j0 + sj + 16 * i;
                int d0 = l0 - jg;     int a0i = d0 < 0 ? -d0 : d0;
                int d1 = d0 + 1;      int a1i = d1 < 0 ? -d1 : d1;
                __half v0 = (l0 >= 1     && l0     <= SEQ) ? wsh[a0i] : __half(0.f);
                __half v1 = (l0 + 1 >= 1 && l0 + 1 <= SEQ) ? wsh[a1i] : __half(0.f);
                Ab[(sj + 16 * i) * (A_STR / 2) + skp] = __halves2half2(v0, v1);
            }
        }
        const uint32_t Bbase = sb + 2 * A_BYTES + (c & 1) * B_BYTES;
#pragma unroll
        for (int q = 0; q < 2; q++) {
            int fi = t + q * THREADS;           // 0..511, 16B slots
            int k  = fi >> 4, c8 = fi & 15;
            int cc = c0 + c8 * 8;
            int n  = cc >> 6, d = cc & 63;
            const __half* src = vtb + ((size_t)n * SS + (k0 + k)) * ROWSTRIDE + d;
            cp_async16(Bbase + (uint32_t)(k * B_STR + c8 * 8) * 2, src);
        }
        CP_COMMIT();
    };

    float acc[2][4][4];
#pragma unroll
    for (int mi = 0; mi < 2; mi++)
#pragma unroll
        for (int ni = 0; ni < 4; ni++)
#pragma unroll
            for (int r = 0; r < 4; r++) acc[mi][ni][r] = 0.f;

    const uint32_t aRow = (uint32_t)(wm * 32 + l15);       // + mi*16
    const uint32_t aKof = (uint32_t)(lhi * 8);             // + ks*16
    const uint32_t bRow = (uint32_t)l15;                   // + ks*16
    const uint32_t bCol = (uint32_t)(wn * 32 + lhi * 8);   // + ni2*16

    stage(0);

    for (int c = 0; c < NCHUNK; c++) {
        CP_WAIT0();
        __syncthreads();
        if (c + 1 < NCHUNK) stage(c + 1);

        const uint32_t Ao = sb + (c & 1) * A_BYTES;
        const uint32_t Bo = sb + 2 * A_BYTES + (c & 1) * B_BYTES;

#pragma unroll
        for (int ks = 0; ks < 2; ks++) {
            uint32_t a[2][4], b[4][2];
#pragma unroll
            for (int mi = 0; mi < 2; mi++)
                ldsm_x4(a[mi], Ao + ((aRow + mi * 16) * A_STR + aKof + ks * 16) * 2);
#pragma unroll
            for (int ni2 = 0; ni2 < 2; ni2++) {
                uint32_t r[4];
                ldsm_x4_t(r, Bo + ((bRow + ks * 16) * B_STR + bCol + ni2 * 16) * 2);
                b[2 * ni2][0] = r[0];      b[2 * ni2][1] = r[1];
                b[2 * ni2 + 1][0] = r[2];  b[2 * ni2 + 1][1] = r[3];
            }
#pragma unroll
            for (int mi = 0; mi < 2; mi++)
#pragma unroll
                for (int ni = 0; ni < 4; ni++)
                    mma_f16(acc[mi][ni], a[mi], b[ni]);
        }
    }

    // ---- epilogue: acc -> out[n, j, h, d]
#pragma unroll
    for (int mi = 0; mi < 2; mi++) {
        const int r0 = j0 + wm * 32 + mi * 16 + g;
#pragma unroll
        for (int ni = 0; ni < 4; ni++) {
            const int cc = c0 + wn * 32 + ni * 8 + 2 * t4;
            const int n = cc >> 6, d = cc & 63;
            float* o = out + (((size_t)n * SS) * NH + h) * ND + d;
            if (r0 >= 1 && r0 <= SEQ) {
                float2 s = make_float2(acc[mi][ni][0], acc[mi][ni][1]);
                *(float2*)(o + (size_t)r0 * NH * ND) = s;
            }
            const int r1 = r0 + 8;
            if (r1 >= 1 && r1 <= SEQ) {
                float2 s = make_float2(acc[mi][ni][2], acc[mi][ni][3]);
                *(float2*)(o + (size_t)r1 * NH * ND) = s;
            }
        }
    }
}

// ---------------------------------------------------------------------------
// blocks 0..11: z_pb scan per head; blocks 12..17: zero pbv border rows
// ---------------------------------------------------------------------------
__global__ __launch_bounds__(1024) void zb_kernel(const float* __restrict__ w,
                                                  float* __restrict__ outz,
                                                  float* __restrict__ out) {
    const int b = blockIdx.x;
    if (b >= NH) {   // border: 6 blocks x 1024 cover 8 segs x 768
        int gidx = (b - NH) * 1024 + threadIdx.x;
        if (gidx < 8 * NH * ND) {
            int seg = gidx / (NH * ND);
            int off = gidx % (NH * ND);
            int n = seg >> 1;
            int j = (seg & 1) ? (SS - 1) : 0;
            out[((size_t)(n * SS + j) * NH * ND) + off] = 0.f;
        }
        return;
    }
    const int h = b;
    __shared__ float buf[2][SS];
    for (int i = threadIdx.x; i < SS; i += 1024)
        buf[0][i] = (i < SEQ) ? w[(size_t)h * SS + i] : 0.f;
    __syncthreads();
    int src = 0;
    for (int off = 1; off < SS; off <<= 1) {
        for (int i = threadIdx.x; i < SS; i += 1024) {
            float val = buf[src][i];
            if (i >= off) val += buf[src][i - off];
            buf[src ^ 1][i] = val;
        }
        src ^= 1;
        __syncthreads();
    }
    const float w0 = buf[src][0];
    for (int l = threadIdx.x; l < SS; l += 1024) {
        float zv = 0.f;
        if (l >= 1 && l <= SEQ)
            zv = buf[src][l - 1] + buf[src][SEQ - l] - w0;
        outz[(size_t)l * NH + h] = zv;
    }
}

// ---------------------------------------------------------------------------
extern "C" void kernel_launch(void* const* d_in, const int* in_sizes, int n_in,
                              void* d_out, int out_size) {
    const float* a0 = (const float*)d_in[0];
    const float* a1 = (const float*)d_in[1];
    const float* v = a0;
    const float* w = a1;
    if (n_in >= 2 && in_sizes[0] < in_sizes[1]) { v = a1; w = a0; }

    float* out  = (float*)d_out;
    float* outz = out + (size_t)SB * SS * NH * ND;

    static int configured = 0;
    if (!configured) {
        cudaFuncSetAttribute(pbv_mma, cudaFuncAttributeMaxDynamicSharedMemorySize,
                             DYN_BYTES);
        configured = 1;
    }

    cvt_kernel<<<NV / (256 * 8), 256>>>(v);
    dim3 grid(SS / TM, 256 / TN, NH);        // 32 x 2 x 12 = 768 CTAs
    pbv_mma<<<grid, THREADS, DYN_BYTES>>>(w, out);
    zb_kernel<<<NH + 6, 1024>>>(w, outz, out);
}